// round 14
// baseline (speedup 1.0000x reference)
#include <cuda_runtime.h>
#include <cuda_fp16.h>
#include <cstdint>
#include <math.h>

#define BATCH 16
#define SEQ   512
#define MTOT  8192          // m = s*16 + b
#define NXG   4096
#define KD    1024

// ---------------- device scratch ----------------
__device__ float  g_X0T[(size_t)KD * MTOT];   // [k][m] (tf32-rounded)
__device__ float  g_YT [(size_t)KD * MTOT];   // [k][m] (rounded)
__device__ float  g_A1T[(size_t)KD * MTOT];   // [k][m] (rounded)
__device__ float  g_A2 [(size_t)MTOT * KD];   // [m][n]
__device__ float  g_XG [(size_t)MTOT * NXG];  // [s][n(4096)][b(16)]
__device__ float  g_Wr [(size_t)NXG * KD];    // rounded weights (current GEMM)
__device__ float  g_bXG[NXG];
__device__ __half g_h16[2][2][BATCH][512];    // [parity][dir][b][k] fp16
__device__ unsigned g_tag[2][64][32];         // per-CTA barrier slots, 128B padded

// ---------------- helpers ----------------
__device__ __forceinline__ unsigned f2tf(float x) {
    unsigned r;
    asm("cvt.rna.tf32.f32 %0, %1;" : "=r"(r) : "f"(x));
    return r;
}
__device__ __forceinline__ float tfr(float x) { return __uint_as_float(f2tf(x)); }

__device__ __forceinline__ void mma_tf32(float& c0, float& c1, float& c2, float& c3,
                                         unsigned a0, unsigned a1, unsigned a2, unsigned a3,
                                         unsigned b0, unsigned b1) {
    asm volatile(
        "mma.sync.aligned.m16n8k8.row.col.f32.tf32.tf32.f32 "
        "{%0,%1,%2,%3},{%4,%5,%6,%7},{%8,%9},{%0,%1,%2,%3};"
        : "+f"(c0), "+f"(c1), "+f"(c2), "+f"(c3)
        : "r"(a0), "r"(a1), "r"(a2), "r"(a3), "r"(b0), "r"(b1));
}
__device__ __forceinline__ void mma_f16(float& c0, float& c1, float& c2, float& c3,
                                        unsigned a0, unsigned a1, unsigned a2, unsigned a3,
                                        unsigned b0, unsigned b1) {
    asm volatile(
        "mma.sync.aligned.m16n8k16.row.col.f32.f16.f16.f32 "
        "{%0,%1,%2,%3},{%4,%5,%6,%7},{%8,%9},{%0,%1,%2,%3};"
        : "+f"(c0), "+f"(c1), "+f"(c2), "+f"(c3)
        : "r"(a0), "r"(a1), "r"(a2), "r"(a3), "r"(b0), "r"(b1));
}
__device__ __forceinline__ void cp16(void* smem, const void* gmem) {
    unsigned s = (unsigned)__cvta_generic_to_shared(smem);
    asm volatile("cp.async.ca.shared.global [%0], [%1], 16;" :: "r"(s), "l"(gmem));
}
__device__ __forceinline__ void cp16cg(void* smem, const void* gmem) {
    unsigned s = (unsigned)__cvta_generic_to_shared(smem);
    asm volatile("cp.async.cg.shared.global [%0], [%1], 16;" :: "r"(s), "l"(gmem));
}
__device__ __forceinline__ void cp_commit() { asm volatile("cp.async.commit_group;"); }
__device__ __forceinline__ void cp_wait1()  { asm volatile("cp.async.wait_group 1;"); }
__device__ __forceinline__ void cp_wait0()  { asm volatile("cp.async.wait_group 0;"); }
__device__ __forceinline__ float sigm(float x) { return 1.0f / (1.0f + __expf(-x)); }

__device__ __forceinline__ unsigned packh2(float a, float b) {
    __half2 h = __floats2half2_rn(a, b);
    return *(unsigned*)&h;
}

// ---------------- k_roundbias: round W into g_Wr (+ bias + tag reset) ----------
__global__ void k_roundbias(const float* __restrict__ src, int n4,
                            const float* __restrict__ bi, const float* __restrict__ bh,
                            int aux) {
    int gid = blockIdx.x * blockDim.x + threadIdx.x;
    if (gid < n4) {
        float4 v = ((const float4*)src)[gid];
        v.x = tfr(v.x); v.y = tfr(v.y); v.z = tfr(v.z); v.w = tfr(v.w);
        ((float4*)g_Wr)[gid] = v;
    } else if (aux) {
        int r = gid - n4;
        if (r < NXG) {
            g_bXG[r] = bi[r] + bh[r];
        } else if (r < NXG + 128) {
            int r2 = r - NXG;
            g_tag[r2 >> 6][r2 & 63][0] = 0u;
        }
    }
}

// ---------------- k_embed: X0T[k][s*16+b] rounded ----------------
__global__ void k_embed(const int* __restrict__ x, const float* __restrict__ lang,
                        const float* __restrict__ emb) {
    __shared__ int toks[BATCH];
    int s = blockIdx.x;
    int tid = threadIdx.x;                      // 256
    if (tid < BATCH) toks[tid] = x[tid * SEQ + s];
    __syncthreads();
    int k = tid * 4;
    float4 v[BATCH];
    if (k < 768) {
        #pragma unroll
        for (int b = 0; b < BATCH; b++)
            v[b] = *(const float4*)(lang + ((size_t)(b * SEQ + s)) * 768 + k);
    } else {
        #pragma unroll
        for (int b = 0; b < BATCH; b++)
            v[b] = *(const float4*)(emb + (size_t)toks[b] * 256 + (k - 768));
    }
    #pragma unroll
    for (int i = 0; i < 4; i++) {
        float* dst = g_X0T + (size_t)(k + i) * MTOT + s * 16;
        #pragma unroll
        for (int bq = 0; bq < 4; bq++) {
            float4 w;
            w.x = tfr(((float*)&v[bq * 4 + 0])[i]);
            w.y = tfr(((float*)&v[bq * 4 + 1])[i]);
            w.z = tfr(((float*)&v[bq * 4 + 2])[i]);
            w.w = tfr(((float*)&v[bq * 4 + 3])[i]);
            *(float4*)(dst + bq * 4) = w;
        }
    }
}

// ---------------- tf32 GEMM: 3-stage cp.async pipeline, ONE sync per k-iter ----
// A: transposed [k][8192] (pre-rounded).  W: g_Wr [N][1024] (pre-rounded).
// CTA tile 128m x 256n, 8 warps (2m x 4n), warp tile 64x64, K-slice 16.
// mode: 0 row-major C[m][N], 1 XG layout, 2 transposed C[n][8192].
#define AST 136
#define BST 20
#define STAGEF 7296                 // floats per stage: A 16*136=2176 + B 256*20=5120
#define GSMEM (3 * STAGEF * 4)      // 87552 bytes

__global__ __launch_bounds__(256, 1)
void k_gemm(int asel, int csel, const float* __restrict__ bias_ext,
            int N, int act, int mode, int rnd) {
    extern __shared__ float sg[];

    const float* A = (asel == 0) ? g_X0T : (asel == 1 ? g_YT : g_A1T);
    const float* bias = bias_ext ? bias_ext : g_bXG;

    int m0 = blockIdx.y * 128;
    int n0 = blockIdx.x * 256;
    int tid = threadIdx.x, lane = tid & 31, warp = tid >> 5;
    int wm = (warp >> 2) * 64;
    int wn = (warp & 3) * 64;

    float acc[4][8][4];
    #pragma unroll
    for (int a = 0; a < 4; a++)
        #pragma unroll
        for (int b = 0; b < 8; b++)
            #pragma unroll
            for (int q = 0; q < 4; q++) acc[a][b][q] = 0.f;

    auto load_slice = [&](int kk, int st) {
        int k0 = kk * 16;
        float* Ad = sg + st * STAGEF;
        float* Bd = Ad + 2176;
        #pragma unroll
        for (int j = 0; j < 2; j++) {
            int id = tid + j * 256;
            int kr = id >> 5, mc = (id & 31) * 4;
            cp16(&Ad[kr * AST + mc], A + (size_t)(k0 + kr) * MTOT + m0 + mc);
        }
        #pragma unroll
        for (int j = 0; j < 4; j++) {
            int id = tid + j * 256;
            int row = id >> 2, kc = (id & 3) * 4;
            cp16(&Bd[row * BST + kc], g_Wr + (size_t)(n0 + row) * KD + k0 + kc);
        }
        cp_commit();
    };

    // prologue: stages 0 and 1 in flight
    load_slice(0, 0);
    load_slice(1, 1);

    #pragma unroll 1
    for (int kk = 0; kk < 64; kk++) {
        if (kk < 63) cp_wait1(); else cp_wait0();
        __syncthreads();
        // issue next load AFTER the sync: all warps finished computing the
        // stage being overwritten ((kk+2)%3 == stage of iter kk-1's... safe:
        // sync guarantees compute of iter kk-1 done; (kk+2)%3 != kk%3).
        if (kk < 62) load_slice(kk + 2, (kk + 2) % 3);

        const float* Ab = sg + (kk % 3) * STAGEF;
        const float* Bb = Ab + 2176;

        #pragma unroll
        for (int kt = 0; kt < 2; kt++) {
            int kc = kt * 8 + (lane & 3);
            unsigned af[4][4];
            #pragma unroll
            for (int mt = 0; mt < 4; mt++) {
                int m = wm + mt * 16 + (lane >> 2);
                af[mt][0] = __float_as_uint(Ab[kc * AST + m]);
                af[mt][1] = __float_as_uint(Ab[kc * AST + m + 8]);
                af[mt][2] = __float_as_uint(Ab[(kc + 4) * AST + m]);
                af[mt][3] = __float_as_uint(Ab[(kc + 4) * AST + m + 8]);
            }
            #pragma unroll
            for (int nt = 0; nt < 8; nt++) {
                int rn = wn + nt * 8 + (lane >> 2);
                unsigned b0 = __float_as_uint(Bb[rn * BST + kc]);
                unsigned b1 = __float_as_uint(Bb[rn * BST + kc + 4]);
                #pragma unroll
                for (int mt = 0; mt < 4; mt++)
                    mma_tf32(acc[mt][nt][0], acc[mt][nt][1], acc[mt][nt][2], acc[mt][nt][3],
                             af[mt][0], af[mt][1], af[mt][2], af[mt][3], b0, b1);
            }
        }
    }

    float* C = (csel == 2) ? g_A1T : (csel == 3 ? g_A2 : g_XG);
    #pragma unroll
    for (int mt = 0; mt < 4; mt++) {
        #pragma unroll
        for (int nt = 0; nt < 8; nt++) {
            int r = m0 + wm + mt * 16 + (lane >> 2);
            int n = n0 + wn + nt * 8 + 2 * (lane & 3);
            float v0 = acc[mt][nt][0] + bias[n];
            float v1 = acc[mt][nt][1] + bias[n + 1];
            float v2 = acc[mt][nt][2] + bias[n];
            float v3 = acc[mt][nt][3] + bias[n + 1];
            if (act) {
                v0 = v0 > 0.f ? v0 : 0.01f * v0;
                v1 = v1 > 0.f ? v1 : 0.01f * v1;
                v2 = v2 > 0.f ? v2 : 0.01f * v2;
                v3 = v3 > 0.f ? v3 : 0.01f * v3;
            }
            if (rnd) { v0 = tfr(v0); v1 = tfr(v1); v2 = tfr(v2); v3 = tfr(v3); }
            if (mode == 1) {
                int s1 = r >> 4, b1v = r & 15;
                int s2 = (r + 8) >> 4, b2v = (r + 8) & 15;
                C[((size_t)s1 * NXG + n) * 16 + b1v]     = v0;
                C[((size_t)s1 * NXG + n + 1) * 16 + b1v] = v1;
                C[((size_t)s2 * NXG + n) * 16 + b2v]     = v2;
                C[((size_t)s2 * NXG + n + 1) * 16 + b2v] = v3;
            } else if (mode == 2) {
                C[(size_t)n * MTOT + r]           = v0;
                C[(size_t)(n + 1) * MTOT + r]     = v1;
                C[(size_t)n * MTOT + r + 8]       = v2;
                C[(size_t)(n + 1) * MTOT + r + 8] = v3;
            } else {
                *(float2*)(C + (size_t)r * N + n)       = make_float2(v0, v1);
                *(float2*)(C + (size_t)(r + 8) * N + n) = make_float2(v2, v3);
            }
        }
    }
}

// ---------------- persistent bidirectional LSTM recurrence (fp16 h) ----------
// BYTE-IDENTICAL to the R4/R13 version (reproducible local optimum).
#define HSTR 520    // halves per batch row in smem (512 + 8 pad)

__global__ __launch_bounds__(256, 1)
void k_rec(const float* __restrict__ Whh, const int* __restrict__ lengths) {
    __shared__ __half hsm[BATCH * HSTR];
    __shared__ float part[4][4][BATCH][9];     // [q][gate][b][u pad9]

    int tid = threadIdx.x, lane = tid & 31, w = tid >> 5;
    int dir = blockIdx.x >> 6;
    int u0 = (blockIdx.x & 63) * 8;
    int q = w & 3, gp = w >> 2;

    // persistent fp16 weight fragments: 2 gates x 8 k16-tiles x 2 regs = 32 regs
    unsigned wH[2][8][2];
    #pragma unroll
    for (int gi = 0; gi < 2; gi++) {
        int g = gp * 2 + gi;
        const float* wr = Whh + ((size_t)(dir * 2048 + g * 512 + u0 + (lane >> 2))) * 512;
        #pragma unroll
        for (int kt = 0; kt < 8; kt++) {
            int kb = q * 128 + kt * 16 + (lane & 3) * 2;
            wH[gi][kt][0] = packh2(wr[kb],     wr[kb + 1]);
            wH[gi][kt][1] = packh2(wr[kb + 8], wr[kb + 9]);
        }
    }

    int ub = tid & 15, uj = (tid >> 4) & 7;    // cell-update ownership (tid<128)
    int len = lengths[ub];
    float hreg = 0.f, creg = 0.f;
    unsigned* myslot = &g_tag[dir][blockIdx.x & 63][0];
    const unsigned* pollslot = &g_tag[dir][tid & 63][0];

    #pragma unroll 1
    for (int t = 0; t < SEQ; t++) {
        int s = dir ? (SEQ - 1 - t) : t;

        // xg for this step (independent of h)
        float xgv[4];
        if (tid < 128) {
            #pragma unroll
            for (int g = 0; g < 4; g++)
                xgv[g] = __ldcg(&g_XG[((size_t)s * NXG + dir * 2048 + g * 512 + u0 + uj) * 16 + ub]);
        }

        float acc[2][4];
        #pragma unroll
        for (int gi = 0; gi < 2; gi++)
            #pragma unroll
            for (int c = 0; c < 4; c++) acc[gi][c] = 0.f;

        if (t > 0) {
            // wait for all producers of h(t-1): poll 64 distributed slots
            if (tid < 64) {
                unsigned v;
                do {
                    asm volatile("ld.acquire.gpu.global.u32 %0, [%1];" : "=r"(v) : "l"(pollslot));
                } while (v < (unsigned)t);
            }
            __syncthreads();

            // stage h(t-1) fp16 (16KB) via cp.async.cg (L2-coherent)
            const __half* src = &g_h16[(t + 1) & 1][dir][0][0];
            #pragma unroll
            for (int j = 0; j < 4; j++) {
                int ch = tid + j * 256;            // 0..1023 16B chunks
                int b = ch >> 6, k8 = (ch & 63) * 8;
                cp16cg(&hsm[b * HSTR + k8], src + ch * 8);
            }
            cp_commit();
            cp_wait0();
            __syncthreads();

            // gates += h @ Whh^T  (8 k16-tiles per warp, 2 gates)
            int b0r = lane >> 2;
            #pragma unroll
            for (int kt = 0; kt < 8; kt++) {
                int kb = q * 128 + kt * 16 + (lane & 3) * 2;
                unsigned a0 = *(const unsigned*)&hsm[b0r * HSTR + kb];
                unsigned a1 = *(const unsigned*)&hsm[(b0r + 8) * HSTR + kb];
                unsigned a2 = *(const unsigned*)&hsm[b0r * HSTR + kb + 8];
                unsigned a3 = *(const unsigned*)&hsm[(b0r + 8) * HSTR + kb + 8];
                #pragma unroll
                for (int gi = 0; gi < 2; gi++)
                    mma_f16(acc[gi][0], acc[gi][1], acc[gi][2], acc[gi][3],
                            a0, a1, a2, a3, wH[gi][kt][0], wH[gi][kt][1]);
            }
        }

        // store partials
        #pragma unroll
        for (int gi = 0; gi < 2; gi++) {
            int g = gp * 2 + gi;
            part[q][g][lane >> 2][2 * (lane & 3)]           = acc[gi][0];
            part[q][g][lane >> 2][2 * (lane & 3) + 1]       = acc[gi][1];
            part[q][g][(lane >> 2) + 8][2 * (lane & 3)]     = acc[gi][2];
            part[q][g][(lane >> 2) + 8][2 * (lane & 3) + 1] = acc[gi][3];
        }
        __syncthreads();

        // cell update (tid < 128)
        if (tid < 128) {
            float v[4];
            #pragma unroll
            for (int g = 0; g < 4; g++)
                v[g] = part[0][g][ub][uj] + part[1][g][ub][uj]
                     + part[2][g][ub][uj] + part[3][g][ub][uj] + xgv[g];
            float gi = sigm(v[0]);
            float gf = sigm(v[1]);
            float gg = tanhf(v[2]);
            float go = sigm(v[3]);
            float cn = gf * creg + gi * gg;
            float hn = go * tanhf(cn);
            bool active = s < len;
            float y = active ? hn : 0.f;
            if (active) { creg = cn; hreg = hn; }

            g_YT[(size_t)(dir * 512 + u0 + uj) * MTOT + s * 16 + ub] = tfr(y);
            unsigned short hb = __half_as_ushort(__float2half_rn(hreg));
            asm volatile("st.global.cg.u16 [%0], %1;"
                         :: "l"(&g_h16[t & 1][dir][ub][u0 + uj]), "h"(hb));
        }
        __syncthreads();

        // publish h(t): release-store step tag to own slot
        if (tid == 0) {
            asm volatile("st.release.gpu.global.u32 [%0], %1;"
                         :: "l"(myslot), "r"((unsigned)(t + 1)));
        }
    }
}

// ---------------- head ----------------
__global__ void k_head(const float* __restrict__ W3, const float* __restrict__ b3,
                       float* __restrict__ out) {
    int gw = (blockIdx.x * blockDim.x + threadIdx.x) >> 5;
    int lane = threadIdx.x & 31;
    if (gw >= MTOT) return;
    const float* a = g_A2 + (size_t)gw * KD;
    float s0 = 0, s1 = 0, s2 = 0, s3 = 0, s4 = 0;
    for (int k = lane; k < KD; k += 32) {
        float v = a[k];
        s0 += v * W3[k];
        s1 += v * W3[1024 + k];
        s2 += v * W3[2048 + k];
        s3 += v * W3[3072 + k];
        s4 += v * W3[4096 + k];
    }
    #pragma unroll
    for (int o = 16; o; o >>= 1) {
        s0 += __shfl_down_sync(0xffffffffu, s0, o);
        s1 += __shfl_down_sync(0xffffffffu, s1, o);
        s2 += __shfl_down_sync(0xffffffffu, s2, o);
        s3 += __shfl_down_sync(0xffffffffu, s3, o);
        s4 += __shfl_down_sync(0xffffffffu, s4, o);
    }
    if (lane == 0) {
        int b = gw & 15, s = gw >> 4;
        float* o = out + ((size_t)b * SEQ + s) * 5;
        o[0] = s0 + b3[0];
        o[1] = s1 + b3[1];
        o[2] = s2 + b3[2];
        o[3] = s3 + b3[3];
        o[4] = s4 + b3[4];
    }
}

// ---------------- launch ----------------
extern "C" void kernel_launch(void* const* d_in, const int* in_sizes, int n_in,
                              void* d_out, int out_size) {
    const int*   x    = (const int*)d_in[0];
    const int*   len  = (const int*)d_in[1];
    const float* lang = (const float*)d_in[2];
    const float* emb  = (const float*)d_in[3];
    const float* W_ih = (const float*)d_in[4];
    const float* W_hh = (const float*)d_in[5];
    const float* b_ih = (const float*)d_in[6];
    const float* b_hh = (const float*)d_in[7];
    const float* W1   = (const float*)d_in[8];
    const float* b1   = (const float*)d_in[9];
    const float* W2   = (const float*)d_in[10];
    const float* b2   = (const float*)d_in[11];
    const float* W3   = (const float*)d_in[12];
    const float* b3   = (const float*)d_in[13];
    float* out = (float*)d_out;

    cudaFuncSetAttribute(k_gemm, cudaFuncAttributeMaxDynamicSharedMemorySize, GSMEM);

    k_embed<<<SEQ, 256>>>(x, lang, emb);

    for (int l = 0; l < 2; l++) {
        // round W_ih[l] + bias + tag reset (aux=1)
        k_roundbias<<<4113, 256>>>(W_ih + (size_t)l * NXG * KD, NXG * KD / 4,
                                   b_ih + (size_t)l * NXG, b_hh + (size_t)l * NXG, 1);
        k_gemm<<<dim3(NXG / 256, MTOT / 128), 256, GSMEM>>>(
            l == 0 ? 0 : 1, 4, nullptr, NXG, 0, 1, 0);
        k_rec<<<128, 256>>>(W_hh + (size_t)l * 2 * 2048 * 512, len);
    }

    k_roundbias<<<1024, 256>>>(W1, KD * KD / 4, nullptr, nullptr, 0);
    k_gemm<<<dim3(KD / 256, MTOT / 128), 256, GSMEM>>>(1, 2, b1, KD, 1, 2, 1);
    k_roundbias<<<1024, 256>>>(W2, KD * KD / 4, nullptr, nullptr, 0);
    k_gemm<<<dim3(KD / 256, MTOT / 128), 256, GSMEM>>>(2, 3, b2, KD, 1, 0, 0);
    k_head<<<MTOT / 8, 256>>>(W3, b3, out);
}

// round 16
// speedup vs baseline: 1.0945x; 1.0945x over previous
#include <cuda_runtime.h>
#include <cuda_fp16.h>
#include <cstdint>
#include <math.h>

#define BATCH 16
#define SEQ   512
#define MTOT  8192          // m = s*16 + b
#define NXG   4096
#define KD    1024

// ---------------- device scratch ----------------
__device__ __align__(256) __half g_X0h[(size_t)MTOT * KD];   // [m][k] fp16
__device__ __align__(256) __half g_Yh [(size_t)MTOT * KD];   // [m][k] fp16
__device__ __align__(256) __half g_A1h[(size_t)MTOT * KD];   // [m][k] fp16
__device__ __align__(256) float  g_A2 [(size_t)MTOT * KD];   // [m][n] fp32
__device__ __align__(256) float  g_XG [(size_t)MTOT * NXG];  // [s][n(4096)][b(16)]
__device__ __align__(256) __half g_Wh [(size_t)NXG * KD];    // fp16 weights (current GEMM)
__device__ float  g_YT [(size_t)KD * MTOT];   // [k][m] float (k_rec output, as R13)
__device__ float  g_bXG[NXG];
__device__ __half g_h16[2][2][BATCH][512];    // [parity][dir][b][k] fp16
__device__ unsigned g_tag[2][64][32];         // per-CTA barrier slots, 128B padded

// ---------------- helpers ----------------
__device__ __forceinline__ unsigned f2tf(float x) {
    unsigned r;
    asm("cvt.rna.tf32.f32 %0, %1;" : "=r"(r) : "f"(x));
    return r;
}
__device__ __forceinline__ float tfr(float x) { return __uint_as_float(f2tf(x)); }

__device__ __forceinline__ void mma_f16(float& c0, float& c1, float& c2, float& c3,
                                        unsigned a0, unsigned a1, unsigned a2, unsigned a3,
                                        unsigned b0, unsigned b1) {
    asm volatile(
        "mma.sync.aligned.m16n8k16.row.col.f32.f16.f16.f32 "
        "{%0,%1,%2,%3},{%4,%5,%6,%7},{%8,%9},{%0,%1,%2,%3};"
        : "+f"(c0), "+f"(c1), "+f"(c2), "+f"(c3)
        : "r"(a0), "r"(a1), "r"(a2), "r"(a3), "r"(b0), "r"(b1));
}
__device__ __forceinline__ void cp16(void* smem, const void* gmem) {
    unsigned s = (unsigned)__cvta_generic_to_shared(smem);
    asm volatile("cp.async.ca.shared.global [%0], [%1], 16;" :: "r"(s), "l"(gmem));
}
__device__ __forceinline__ void cp16cg(void* smem, const void* gmem) {
    unsigned s = (unsigned)__cvta_generic_to_shared(smem);
    asm volatile("cp.async.cg.shared.global [%0], [%1], 16;" :: "r"(s), "l"(gmem));
}
__device__ __forceinline__ void cp_commit() { asm volatile("cp.async.commit_group;"); }
__device__ __forceinline__ void cp_wait1()  { asm volatile("cp.async.wait_group 1;"); }
__device__ __forceinline__ void cp_wait0()  { asm volatile("cp.async.wait_group 0;"); }
__device__ __forceinline__ float sigm(float x) { return 1.0f / (1.0f + __expf(-x)); }
__device__ __forceinline__ unsigned packh2(float a, float b) {
    __half2 h = __floats2half2_rn(a, b);
    return *(unsigned*)&h;
}

// ---------------- k_cvtW: W fp32 -> g_Wh fp16 (+ bias + tag reset) ----------
__global__ void k_cvtW(const float* __restrict__ src, int n4,
                       const float* __restrict__ bi, const float* __restrict__ bh,
                       int aux) {
    int gid = blockIdx.x * blockDim.x + threadIdx.x;
    if (gid < n4) {
        float4 v = ((const float4*)src)[gid];
        uint2 o;
        o.x = packh2(v.x, v.y);
        o.y = packh2(v.z, v.w);
        ((uint2*)g_Wh)[gid] = o;
    } else if (aux) {
        int r = gid - n4;
        if (r < NXG) {
            g_bXG[r] = bi[r] + bh[r];
        } else if (r < NXG + 128) {
            int r2 = r - NXG;
            g_tag[r2 >> 6][r2 & 63][0] = 0u;
        }
    }
}

// ---------------- k_embed: X0h[m][k] fp16 ----------------
__global__ void k_embed(const int* __restrict__ x, const float* __restrict__ lang,
                        const float* __restrict__ emb) {
    __shared__ int toks[BATCH];
    int s = blockIdx.x;
    int tid = threadIdx.x;                      // 256
    if (tid < BATCH) toks[tid] = x[tid * SEQ + s];
    __syncthreads();
    int k = tid * 4;
    #pragma unroll 4
    for (int b = 0; b < BATCH; b++) {
        float4 v;
        if (k < 768) v = *(const float4*)(lang + ((size_t)(b * SEQ + s)) * 768 + k);
        else         v = *(const float4*)(emb + (size_t)toks[b] * 256 + (k - 768));
        uint2 o;
        o.x = packh2(v.x, v.y);
        o.y = packh2(v.z, v.w);
        *(uint2*)&g_X0h[(size_t)(s * 16 + b) * KD + k] = o;
    }
}

// ---------------- k_t: g_YT [k][m] float -> g_Yh [m][k] fp16 ----------------
__global__ void k_t() {
    __shared__ float ts[64][65];
    int k0 = blockIdx.x * 64;
    int m0 = blockIdx.y * 64;
    int tid = threadIdx.x;
    #pragma unroll
    for (int p = 0; p < 16; p++) {
        int id = tid + p * 256;
        int kr = id >> 6, mc = id & 63;
        ts[kr][mc] = g_YT[(size_t)(k0 + kr) * MTOT + m0 + mc];
    }
    __syncthreads();
    #pragma unroll
    for (int p = 0; p < 16; p++) {
        int id = tid + p * 256;
        int mr = id >> 6, kc = id & 63;
        g_Yh[(size_t)(m0 + mr) * KD + k0 + kc] = __float2half_rn(ts[kc][mr]);
    }
}

// ---------------- fp16 GEMM: C[m][n] = A[m][:] . W[n][:] + bias[n] ----------
// A: [8192][1024] fp16 row-major. W: g_Wh [N][1024] fp16. K=1024.
// CTA 128m x 256n, 8 warps (2m x 4n), warp 64x64, K-slice 16.
// mode: 1 -> XG layout fp32; 0 -> fp32 row-major; 3 -> fp16 row-major.
#define AST2 24   // halves per smem row (16 + 8 pad)

__global__ __launch_bounds__(256, 1)
void k_gemm(int asel, const float* __restrict__ bias_ext,
            int N, int act, int mode) {
    __shared__ __half As[2][128 * AST2];
    __shared__ __half Bs[2][256 * AST2];

    const __half* A = (asel == 0) ? g_X0h : (asel == 1 ? g_Yh : g_A1h);
    const float* bias = bias_ext ? bias_ext : g_bXG;

    int m0 = blockIdx.y * 128;
    int n0 = blockIdx.x * 256;
    int tid = threadIdx.x, lane = tid & 31, warp = tid >> 5;
    int wm = (warp >> 2) * 64;
    int wn = (warp & 3) * 64;

    float acc[4][8][4];
    #pragma unroll
    for (int a = 0; a < 4; a++)
        #pragma unroll
        for (int b = 0; b < 8; b++)
            #pragma unroll
            for (int q = 0; q < 4; q++) acc[a][b][q] = 0.f;

    auto load_slice = [&](int kk, int buf) {
        int k0 = kk * 16;
        __half* Ad = As[buf];
        __half* Bd = Bs[buf];
        {
            int row = tid >> 1, h8 = (tid & 1) * 8;
            cp16(&Ad[row * AST2 + h8], A + (size_t)(m0 + row) * KD + k0 + h8);
        }
        #pragma unroll
        for (int j = 0; j < 2; j++) {
            int id = tid + j * 256;
            int row = id >> 1, h8 = (id & 1) * 8;
            cp16(&Bd[row * AST2 + h8], g_Wh + (size_t)(n0 + row) * KD + k0 + h8);
        }
        cp_commit();
    };

    load_slice(0, 0);

    #pragma unroll 1
    for (int kk = 0; kk < 64; kk++) {
        int buf = kk & 1;
        if (kk < 63) load_slice(kk + 1, buf ^ 1);
        if (kk < 63) cp_wait1(); else cp_wait0();
        __syncthreads();
        const __half* Ab = As[buf];
        const __half* Bb = Bs[buf];

        unsigned af[4][4];
        int kq = 2 * (lane & 3);
        #pragma unroll
        for (int mt = 0; mt < 4; mt++) {
            int r = wm + mt * 16 + (lane >> 2);
            af[mt][0] = *(const unsigned*)&Ab[r * AST2 + kq];
            af[mt][1] = *(const unsigned*)&Ab[(r + 8) * AST2 + kq];
            af[mt][2] = *(const unsigned*)&Ab[r * AST2 + kq + 8];
            af[mt][3] = *(const unsigned*)&Ab[(r + 8) * AST2 + kq + 8];
        }
        #pragma unroll
        for (int nt = 0; nt < 8; nt++) {
            int rn = wn + nt * 8 + (lane >> 2);
            unsigned b0 = *(const unsigned*)&Bb[rn * AST2 + kq];
            unsigned b1 = *(const unsigned*)&Bb[rn * AST2 + kq + 8];
            #pragma unroll
            for (int mt = 0; mt < 4; mt++)
                mma_f16(acc[mt][nt][0], acc[mt][nt][1], acc[mt][nt][2], acc[mt][nt][3],
                        af[mt][0], af[mt][1], af[mt][2], af[mt][3], b0, b1);
        }
        __syncthreads();
    }

    #pragma unroll
    for (int mt = 0; mt < 4; mt++) {
        #pragma unroll
        for (int nt = 0; nt < 8; nt++) {
            int r = m0 + wm + mt * 16 + (lane >> 2);
            int n = n0 + wn + nt * 8 + 2 * (lane & 3);
            float v0 = acc[mt][nt][0] + bias[n];
            float v1 = acc[mt][nt][1] + bias[n + 1];
            float v2 = acc[mt][nt][2] + bias[n];
            float v3 = acc[mt][nt][3] + bias[n + 1];
            if (act) {
                v0 = v0 > 0.f ? v0 : 0.01f * v0;
                v1 = v1 > 0.f ? v1 : 0.01f * v1;
                v2 = v2 > 0.f ? v2 : 0.01f * v2;
                v3 = v3 > 0.f ? v3 : 0.01f * v3;
            }
            if (mode == 1) {
                int s1 = r >> 4, b1v = r & 15;
                int s2 = (r + 8) >> 4, b2v = (r + 8) & 15;
                g_XG[((size_t)s1 * NXG + n) * 16 + b1v]     = v0;
                g_XG[((size_t)s1 * NXG + n + 1) * 16 + b1v] = v1;
                g_XG[((size_t)s2 * NXG + n) * 16 + b2v]     = v2;
                g_XG[((size_t)s2 * NXG + n + 1) * 16 + b2v] = v3;
            } else if (mode == 3) {
                *(unsigned*)&g_A1h[(size_t)r * KD + n]       = packh2(v0, v1);
                *(unsigned*)&g_A1h[(size_t)(r + 8) * KD + n] = packh2(v2, v3);
            } else {
                *(float2*)(g_A2 + (size_t)r * N + n)       = make_float2(v0, v1);
                *(float2*)(g_A2 + (size_t)(r + 8) * N + n) = make_float2(v2, v3);
            }
        }
    }
}

// ---------------- persistent bidirectional LSTM recurrence (fp16 h) ----------
// BYTE-IDENTICAL to the R4/R13 version (reproducible local optimum).
#define HSTR 520    // halves per batch row in smem (512 + 8 pad)

__global__ __launch_bounds__(256, 1)
void k_rec(const float* __restrict__ Whh, const int* __restrict__ lengths) {
    __shared__ __half hsm[BATCH * HSTR];
    __shared__ float part[4][4][BATCH][9];     // [q][gate][b][u pad9]

    int tid = threadIdx.x, lane = tid & 31, w = tid >> 5;
    int dir = blockIdx.x >> 6;
    int u0 = (blockIdx.x & 63) * 8;
    int q = w & 3, gp = w >> 2;

    // persistent fp16 weight fragments: 2 gates x 8 k16-tiles x 2 regs = 32 regs
    unsigned wH[2][8][2];
    #pragma unroll
    for (int gi = 0; gi < 2; gi++) {
        int g = gp * 2 + gi;
        const float* wr = Whh + ((size_t)(dir * 2048 + g * 512 + u0 + (lane >> 2))) * 512;
        #pragma unroll
        for (int kt = 0; kt < 8; kt++) {
            int kb = q * 128 + kt * 16 + (lane & 3) * 2;
            wH[gi][kt][0] = packh2(wr[kb],     wr[kb + 1]);
            wH[gi][kt][1] = packh2(wr[kb + 8], wr[kb + 9]);
        }
    }

    int ub = tid & 15, uj = (tid >> 4) & 7;    // cell-update ownership (tid<128)
    int len = lengths[ub];
    float hreg = 0.f, creg = 0.f;
    unsigned* myslot = &g_tag[dir][blockIdx.x & 63][0];
    const unsigned* pollslot = &g_tag[dir][tid & 63][0];

    #pragma unroll 1
    for (int t = 0; t < SEQ; t++) {
        int s = dir ? (SEQ - 1 - t) : t;

        // xg for this step (independent of h)
        float xgv[4];
        if (tid < 128) {
            #pragma unroll
            for (int g = 0; g < 4; g++)
                xgv[g] = __ldcg(&g_XG[((size_t)s * NXG + dir * 2048 + g * 512 + u0 + uj) * 16 + ub]);
        }

        float acc[2][4];
        #pragma unroll
        for (int gi = 0; gi < 2; gi++)
            #pragma unroll
            for (int c = 0; c < 4; c++) acc[gi][c] = 0.f;

        if (t > 0) {
            // wait for all producers of h(t-1): poll 64 distributed slots
            if (tid < 64) {
                unsigned v;
                do {
                    asm volatile("ld.acquire.gpu.global.u32 %0, [%1];" : "=r"(v) : "l"(pollslot));
                } while (v < (unsigned)t);
            }
            __syncthreads();

            // stage h(t-1) fp16 (16KB) via cp.async.cg (L2-coherent)
            const __half* src = &g_h16[(t + 1) & 1][dir][0][0];
            #pragma unroll
            for (int j = 0; j < 4; j++) {
                int ch = tid + j * 256;            // 0..1023 16B chunks
                int b = ch >> 6, k8 = (ch & 63) * 8;
                cp16cg(&hsm[b * HSTR + k8], src + ch * 8);
            }
            cp_commit();
            cp_wait0();
            __syncthreads();

            // gates += h @ Whh^T  (8 k16-tiles per warp, 2 gates)
            int b0r = lane >> 2;
            #pragma unroll
            for (int kt = 0; kt < 8; kt++) {
                int kb = q * 128 + kt * 16 + (lane & 3) * 2;
                unsigned a0 = *(const unsigned*)&hsm[b0r * HSTR + kb];
                unsigned a1 = *(const unsigned*)&hsm[(b0r + 8) * HSTR + kb];
                unsigned a2 = *(const unsigned*)&hsm[b0r * HSTR + kb + 8];
                unsigned a3 = *(const unsigned*)&hsm[(b0r + 8) * HSTR + kb + 8];
                #pragma unroll
                for (int gi = 0; gi < 2; gi++)
                    mma_f16(acc[gi][0], acc[gi][1], acc[gi][2], acc[gi][3],
                            a0, a1, a2, a3, wH[gi][kt][0], wH[gi][kt][1]);
            }
        }

        // store partials
        #pragma unroll
        for (int gi = 0; gi < 2; gi++) {
            int g = gp * 2 + gi;
            part[q][g][lane >> 2][2 * (lane & 3)]           = acc[gi][0];
            part[q][g][lane >> 2][2 * (lane & 3) + 1]       = acc[gi][1];
            part[q][g][(lane >> 2) + 8][2 * (lane & 3)]     = acc[gi][2];
            part[q][g][(lane >> 2) + 8][2 * (lane & 3) + 1] = acc[gi][3];
        }
        __syncthreads();

        // cell update (tid < 128)
        if (tid < 128) {
            float v[4];
            #pragma unroll
            for (int g = 0; g < 4; g++)
                v[g] = part[0][g][ub][uj] + part[1][g][ub][uj]
                     + part[2][g][ub][uj] + part[3][g][ub][uj] + xgv[g];
            float gi = sigm(v[0]);
            float gf = sigm(v[1]);
            float gg = tanhf(v[2]);
            float go = sigm(v[3]);
            float cn = gf * creg + gi * gg;
            float hn = go * tanhf(cn);
            bool active = s < len;
            float y = active ? hn : 0.f;
            if (active) { creg = cn; hreg = hn; }

            g_YT[(size_t)(dir * 512 + u0 + uj) * MTOT + s * 16 + ub] = tfr(y);
            unsigned short hb = __half_as_ushort(__float2half_rn(hreg));
            asm volatile("st.global.cg.u16 [%0], %1;"
                         :: "l"(&g_h16[t & 1][dir][ub][u0 + uj]), "h"(hb));
        }
        __syncthreads();

        // publish h(t): release-store step tag to own slot
        if (tid == 0) {
            asm volatile("st.release.gpu.global.u32 [%0], %1;"
                         :: "l"(myslot), "r"((unsigned)(t + 1)));
        }
    }
}

// ---------------- head ----------------
__global__ void k_head(const float* __restrict__ W3, const float* __restrict__ b3,
                       float* __restrict__ out) {
    int gw = (blockIdx.x * blockDim.x + threadIdx.x) >> 5;
    int lane = threadIdx.x & 31;
    if (gw >= MTOT) return;
    const float* a = g_A2 + (size_t)gw * KD;
    float s0 = 0, s1 = 0, s2 = 0, s3 = 0, s4 = 0;
    for (int k = lane; k < KD; k += 32) {
        float v = a[k];
        s0 += v * W3[k];
        s1 += v * W3[1024 + k];
        s2 += v * W3[2048 + k];
        s3 += v * W3[3072 + k];
        s4 += v * W3[4096 + k];
    }
    #pragma unroll
    for (int o = 16; o; o >>= 1) {
        s0 += __shfl_down_sync(0xffffffffu, s0, o);
        s1 += __shfl_down_sync(0xffffffffu, s1, o);
        s2 += __shfl_down_sync(0xffffffffu, s2, o);
        s3 += __shfl_down_sync(0xffffffffu, s3, o);
        s4 += __shfl_down_sync(0xffffffffu, s4, o);
    }
    if (lane == 0) {
        int b = gw & 15, s = gw >> 4;
        float* o = out + ((size_t)b * SEQ + s) * 5;
        o[0] = s0 + b3[0];
        o[1] = s1 + b3[1];
        o[2] = s2 + b3[2];
        o[3] = s3 + b3[3];
        o[4] = s4 + b3[4];
    }
}

// ---------------- launch ----------------
extern "C" void kernel_launch(void* const* d_in, const int* in_sizes, int n_in,
                              void* d_out, int out_size) {
    const int*   x    = (const int*)d_in[0];
    const int*   len  = (const int*)d_in[1];
    const float* lang = (const float*)d_in[2];
    const float* emb  = (const float*)d_in[3];
    const float* W_ih = (const float*)d_in[4];
    const float* W_hh = (const float*)d_in[5];
    const float* b_ih = (const float*)d_in[6];
    const float* b_hh = (const float*)d_in[7];
    const float* W1   = (const float*)d_in[8];
    const float* b1   = (const float*)d_in[9];
    const float* W2   = (const float*)d_in[10];
    const float* b2   = (const float*)d_in[11];
    const float* W3   = (const float*)d_in[12];
    const float* b3   = (const float*)d_in[13];
    float* out = (float*)d_out;

    k_embed<<<SEQ, 256>>>(x, lang, emb);

    for (int l = 0; l < 2; l++) {
        // W_ih[l] fp16 + bias + tag reset
        k_cvtW<<<4113, 256>>>(W_ih + (size_t)l * NXG * KD, NXG * KD / 4,
                              b_ih + (size_t)l * NXG, b_hh + (size_t)l * NXG, 1);
        k_gemm<<<dim3(NXG / 256, MTOT / 128), 256>>>(l == 0 ? 0 : 1, nullptr, NXG, 0, 1);
        k_rec<<<128, 256>>>(W_hh + (size_t)l * 2 * 2048 * 512, len);
        // bridge: g_YT [k][m] float -> g_Yh [m][k] fp16 (feeds next GEMM)
        k_t<<<dim3(16, 128), 256>>>();
    }

    k_cvtW<<<1024, 256>>>(W1, KD * KD / 4, nullptr, nullptr, 0);
    k_gemm<<<dim3(KD / 256, MTOT / 128), 256>>>(1, b1, KD, 1, 3);
    k_cvtW<<<1024, 256>>>(W2, KD * KD / 4, nullptr, nullptr, 0);
    k_gemm<<<dim3(KD / 256, MTOT / 128), 256>>>(2, b2, KD, 1, 0);
    k_head<<<MTOT / 8, 256>>>(W3, b3, out);
}

// round 17
// speedup vs baseline: 1.1033x; 1.0080x over previous
#include <cuda_runtime.h>
#include <cuda_fp16.h>
#include <cstdint>
#include <math.h>

#define BATCH 16
#define SEQ   512
#define MTOT  8192          // m = s*16 + b
#define NXG   4096
#define KD    1024

// ---------------- device scratch ----------------
__device__ __align__(256) __half g_X0h[(size_t)MTOT * KD];   // [m][k] fp16
__device__ __align__(256) __half g_Yh [(size_t)MTOT * KD];   // [m][k] fp16
__device__ __align__(256) __half g_A1h[(size_t)MTOT * KD];   // [m][k] fp16
__device__ __align__(256) float  g_A2 [(size_t)MTOT * KD];   // [m][n] fp32
__device__ __align__(256) float  g_XG [(size_t)MTOT * NXG];  // [s][n(4096)][b(16)]
__device__ __align__(256) __half g_Wh [(size_t)NXG * KD];    // fp16 weights (current GEMM)
__device__ float  g_YT [(size_t)KD * MTOT];   // [k][m] float (k_rec output)
__device__ float  g_bXG[NXG];
__device__ __half g_h16[2][2][BATCH][512];    // [parity][dir][b][k] fp16
__device__ unsigned g_tag[2][64][32];         // per-CTA barrier slots, 128B padded

// ---------------- helpers ----------------
__device__ __forceinline__ unsigned f2tf(float x) {
    unsigned r;
    asm("cvt.rna.tf32.f32 %0, %1;" : "=r"(r) : "f"(x));
    return r;
}
__device__ __forceinline__ float tfr(float x) { return __uint_as_float(f2tf(x)); }

__device__ __forceinline__ void mma_f16(float& c0, float& c1, float& c2, float& c3,
                                        unsigned a0, unsigned a1, unsigned a2, unsigned a3,
                                        unsigned b0, unsigned b1) {
    asm volatile(
        "mma.sync.aligned.m16n8k16.row.col.f32.f16.f16.f32 "
        "{%0,%1,%2,%3},{%4,%5,%6,%7},{%8,%9},{%0,%1,%2,%3};"
        : "+f"(c0), "+f"(c1), "+f"(c2), "+f"(c3)
        : "r"(a0), "r"(a1), "r"(a2), "r"(a3), "r"(b0), "r"(b1));
}
__device__ __forceinline__ void cp16(void* smem, const void* gmem) {
    unsigned s = (unsigned)__cvta_generic_to_shared(smem);
    asm volatile("cp.async.ca.shared.global [%0], [%1], 16;" :: "r"(s), "l"(gmem));
}
__device__ __forceinline__ void cp16cg(void* smem, const void* gmem) {
    unsigned s = (unsigned)__cvta_generic_to_shared(smem);
    asm volatile("cp.async.cg.shared.global [%0], [%1], 16;" :: "r"(s), "l"(gmem));
}
__device__ __forceinline__ void cp_commit() { asm volatile("cp.async.commit_group;"); }
__device__ __forceinline__ void cp_wait1()  { asm volatile("cp.async.wait_group 1;"); }
__device__ __forceinline__ void cp_wait0()  { asm volatile("cp.async.wait_group 0;"); }
__device__ __forceinline__ float sigm(float x) { return 1.0f / (1.0f + __expf(-x)); }
__device__ __forceinline__ unsigned packh2(float a, float b) {
    __half2 h = __floats2half2_rn(a, b);
    return *(unsigned*)&h;
}

// ---------------- k_cvtW: W fp32 -> g_Wh fp16 (+ bias + tag reset) ----------
__global__ void k_cvtW(const float* __restrict__ src, int n4,
                       const float* __restrict__ bi, const float* __restrict__ bh,
                       int aux) {
    int gid = blockIdx.x * blockDim.x + threadIdx.x;
    if (gid < n4) {
        float4 v = ((const float4*)src)[gid];
        uint2 o;
        o.x = packh2(v.x, v.y);
        o.y = packh2(v.z, v.w);
        ((uint2*)g_Wh)[gid] = o;
    } else if (aux) {
        int r = gid - n4;
        if (r < NXG) {
            g_bXG[r] = bi[r] + bh[r];
        } else if (r < NXG + 128) {
            int r2 = r - NXG;
            g_tag[r2 >> 6][r2 & 63][0] = 0u;
        }
    }
}

// ---------------- k_embed: X0h[m][k] fp16 ----------------
__global__ void k_embed(const int* __restrict__ x, const float* __restrict__ lang,
                        const float* __restrict__ emb) {
    __shared__ int toks[BATCH];
    int s = blockIdx.x;
    int tid = threadIdx.x;                      // 256
    if (tid < BATCH) toks[tid] = x[tid * SEQ + s];
    __syncthreads();
    int k = tid * 4;
    #pragma unroll 4
    for (int b = 0; b < BATCH; b++) {
        float4 v;
        if (k < 768) v = *(const float4*)(lang + ((size_t)(b * SEQ + s)) * 768 + k);
        else         v = *(const float4*)(emb + (size_t)toks[b] * 256 + (k - 768));
        uint2 o;
        o.x = packh2(v.x, v.y);
        o.y = packh2(v.z, v.w);
        *(uint2*)&g_X0h[(size_t)(s * 16 + b) * KD + k] = o;
    }
}

// ---------------- k_t: g_YT [k][m] float -> g_Yh [m][k] fp16 ----------------
__global__ void k_t() {
    __shared__ float ts[64][65];
    int k0 = blockIdx.x * 64;
    int m0 = blockIdx.y * 64;
    int tid = threadIdx.x;
    #pragma unroll
    for (int p = 0; p < 16; p++) {
        int id = tid + p * 256;
        int kr = id >> 6, mc = id & 63;
        ts[kr][mc] = g_YT[(size_t)(k0 + kr) * MTOT + m0 + mc];
    }
    __syncthreads();
    #pragma unroll
    for (int p = 0; p < 16; p++) {
        int id = tid + p * 256;
        int mr = id >> 6, kc = id & 63;
        g_Yh[(size_t)(m0 + mr) * KD + k0 + kc] = __float2half_rn(ts[kc][mr]);
    }
}

// ---------------- fp16 GEMM: C[m][n] = A[m][:] . W[n][:] + bias[n] ----------
// A: [8192][1024] fp16 row-major. W: g_Wh [N][1024] fp16. K=1024.
// CTA 128m x 256n, 8 warps (2m x 4n), warp 64x64, K-slice 16.
// mode: 1 -> XG layout fp32; 0 -> fp32 row-major; 3 -> fp16 row-major.
#define AST2 24   // halves per smem row (16 + 8 pad)

__global__ __launch_bounds__(256, 1)
void k_gemm(int asel, const float* __restrict__ bias_ext,
            int N, int act, int mode) {
    __shared__ __half As[2][128 * AST2];
    __shared__ __half Bs[2][256 * AST2];

    const __half* A = (asel == 0) ? g_X0h : (asel == 1 ? g_Yh : g_A1h);
    const float* bias = bias_ext ? bias_ext : g_bXG;

    int m0 = blockIdx.y * 128;
    int n0 = blockIdx.x * 256;
    int tid = threadIdx.x, lane = tid & 31, warp = tid >> 5;
    int wm = (warp >> 2) * 64;
    int wn = (warp & 3) * 64;

    float acc[4][8][4];
    #pragma unroll
    for (int a = 0; a < 4; a++)
        #pragma unroll
        for (int b = 0; b < 8; b++)
            #pragma unroll
            for (int q = 0; q < 4; q++) acc[a][b][q] = 0.f;

    auto load_slice = [&](int kk, int buf) {
        int k0 = kk * 16;
        __half* Ad = As[buf];
        __half* Bd = Bs[buf];
        {
            int row = tid >> 1, h8 = (tid & 1) * 8;
            cp16(&Ad[row * AST2 + h8], A + (size_t)(m0 + row) * KD + k0 + h8);
        }
        #pragma unroll
        for (int j = 0; j < 2; j++) {
            int id = tid + j * 256;
            int row = id >> 1, h8 = (id & 1) * 8;
            cp16(&Bd[row * AST2 + h8], g_Wh + (size_t)(n0 + row) * KD + k0 + h8);
        }
        cp_commit();
    };

    load_slice(0, 0);

    #pragma unroll 1
    for (int kk = 0; kk < 64; kk++) {
        int buf = kk & 1;
        if (kk < 63) load_slice(kk + 1, buf ^ 1);
        if (kk < 63) cp_wait1(); else cp_wait0();
        __syncthreads();
        const __half* Ab = As[buf];
        const __half* Bb = Bs[buf];

        unsigned af[4][4];
        int kq = 2 * (lane & 3);
        #pragma unroll
        for (int mt = 0; mt < 4; mt++) {
            int r = wm + mt * 16 + (lane >> 2);
            af[mt][0] = *(const unsigned*)&Ab[r * AST2 + kq];
            af[mt][1] = *(const unsigned*)&Ab[(r + 8) * AST2 + kq];
            af[mt][2] = *(const unsigned*)&Ab[r * AST2 + kq + 8];
            af[mt][3] = *(const unsigned*)&Ab[(r + 8) * AST2 + kq + 8];
        }
        #pragma unroll
        for (int nt = 0; nt < 8; nt++) {
            int rn = wn + nt * 8 + (lane >> 2);
            unsigned b0 = *(const unsigned*)&Bb[rn * AST2 + kq];
            unsigned b1 = *(const unsigned*)&Bb[rn * AST2 + kq + 8];
            #pragma unroll
            for (int mt = 0; mt < 4; mt++)
                mma_f16(acc[mt][nt][0], acc[mt][nt][1], acc[mt][nt][2], acc[mt][nt][3],
                        af[mt][0], af[mt][1], af[mt][2], af[mt][3], b0, b1);
        }
        __syncthreads();
    }

    #pragma unroll
    for (int mt = 0; mt < 4; mt++) {
        #pragma unroll
        for (int nt = 0; nt < 8; nt++) {
            int r = m0 + wm + mt * 16 + (lane >> 2);
            int n = n0 + wn + nt * 8 + 2 * (lane & 3);
            float v0 = acc[mt][nt][0] + bias[n];
            float v1 = acc[mt][nt][1] + bias[n + 1];
            float v2 = acc[mt][nt][2] + bias[n];
            float v3 = acc[mt][nt][3] + bias[n + 1];
            if (act) {
                v0 = v0 > 0.f ? v0 : 0.01f * v0;
                v1 = v1 > 0.f ? v1 : 0.01f * v1;
                v2 = v2 > 0.f ? v2 : 0.01f * v2;
                v3 = v3 > 0.f ? v3 : 0.01f * v3;
            }
            if (mode == 1) {
                int s1 = r >> 4, b1v = r & 15;
                int s2 = (r + 8) >> 4, b2v = (r + 8) & 15;
                g_XG[((size_t)s1 * NXG + n) * 16 + b1v]     = v0;
                g_XG[((size_t)s1 * NXG + n + 1) * 16 + b1v] = v1;
                g_XG[((size_t)s2 * NXG + n) * 16 + b2v]     = v2;
                g_XG[((size_t)s2 * NXG + n + 1) * 16 + b2v] = v3;
            } else if (mode == 3) {
                *(unsigned*)&g_A1h[(size_t)r * KD + n]       = packh2(v0, v1);
                *(unsigned*)&g_A1h[(size_t)(r + 8) * KD + n] = packh2(v2, v3);
            } else {
                *(float2*)(g_A2 + (size_t)r * N + n)       = make_float2(v0, v1);
                *(float2*)(g_A2 + (size_t)(r + 8) * N + n) = make_float2(v2, v3);
            }
        }
    }
}

// ---------------- persistent bidirectional LSTM recurrence (fp16 h) ----------
// R13 version with ONE change: y publish moved AFTER the release store
// (y held in a register; removes ~8 L2 sector-drains from the release chain).
#define HSTR 520    // halves per batch row in smem (512 + 8 pad)

__global__ __launch_bounds__(256, 1)
void k_rec(const float* __restrict__ Whh, const int* __restrict__ lengths) {
    __shared__ __half hsm[BATCH * HSTR];
    __shared__ float part[4][4][BATCH][9];     // [q][gate][b][u pad9]

    int tid = threadIdx.x, lane = tid & 31, w = tid >> 5;
    int dir = blockIdx.x >> 6;
    int u0 = (blockIdx.x & 63) * 8;
    int q = w & 3, gp = w >> 2;

    // persistent fp16 weight fragments: 2 gates x 8 k16-tiles x 2 regs = 32 regs
    unsigned wH[2][8][2];
    #pragma unroll
    for (int gi = 0; gi < 2; gi++) {
        int g = gp * 2 + gi;
        const float* wr = Whh + ((size_t)(dir * 2048 + g * 512 + u0 + (lane >> 2))) * 512;
        #pragma unroll
        for (int kt = 0; kt < 8; kt++) {
            int kb = q * 128 + kt * 16 + (lane & 3) * 2;
            wH[gi][kt][0] = packh2(wr[kb],     wr[kb + 1]);
            wH[gi][kt][1] = packh2(wr[kb + 8], wr[kb + 9]);
        }
    }

    int ub = tid & 15, uj = (tid >> 4) & 7;    // cell-update ownership (tid<128)
    int len = lengths[ub];
    float hreg = 0.f, creg = 0.f;
    unsigned* myslot = &g_tag[dir][blockIdx.x & 63][0];
    const unsigned* pollslot = &g_tag[dir][tid & 63][0];

    #pragma unroll 1
    for (int t = 0; t < SEQ; t++) {
        int s = dir ? (SEQ - 1 - t) : t;

        // xg for this step (independent of h)
        float xgv[4];
        if (tid < 128) {
            #pragma unroll
            for (int g = 0; g < 4; g++)
                xgv[g] = __ldcg(&g_XG[((size_t)s * NXG + dir * 2048 + g * 512 + u0 + uj) * 16 + ub]);
        }

        float acc[2][4];
        #pragma unroll
        for (int gi = 0; gi < 2; gi++)
            #pragma unroll
            for (int c = 0; c < 4; c++) acc[gi][c] = 0.f;

        if (t > 0) {
            // wait for all producers of h(t-1): poll 64 distributed slots
            if (tid < 64) {
                unsigned v;
                do {
                    asm volatile("ld.acquire.gpu.global.u32 %0, [%1];" : "=r"(v) : "l"(pollslot));
                } while (v < (unsigned)t);
            }
            __syncthreads();

            // stage h(t-1) fp16 (16KB) via cp.async.cg (L2-coherent)
            const __half* src = &g_h16[(t + 1) & 1][dir][0][0];
            #pragma unroll
            for (int j = 0; j < 4; j++) {
                int ch = tid + j * 256;            // 0..1023 16B chunks
                int b = ch >> 6, k8 = (ch & 63) * 8;
                cp16cg(&hsm[b * HSTR + k8], src + ch * 8);
            }
            cp_commit();
            cp_wait0();
            __syncthreads();

            // gates += h @ Whh^T  (8 k16-tiles per warp, 2 gates)
            int b0r = lane >> 2;
            #pragma unroll
            for (int kt = 0; kt < 8; kt++) {
                int kb = q * 128 + kt * 16 + (lane & 3) * 2;
                unsigned a0 = *(const unsigned*)&hsm[b0r * HSTR + kb];
                unsigned a1 = *(const unsigned*)&hsm[(b0r + 8) * HSTR + kb];
                unsigned a2 = *(const unsigned*)&hsm[b0r * HSTR + kb + 8];
                unsigned a3 = *(const unsigned*)&hsm[(b0r + 8) * HSTR + kb + 8];
                #pragma unroll
                for (int gi = 0; gi < 2; gi++)
                    mma_f16(acc[gi][0], acc[gi][1], acc[gi][2], acc[gi][3],
                            a0, a1, a2, a3, wH[gi][kt][0], wH[gi][kt][1]);
            }
        }

        // store partials
        #pragma unroll
        for (int gi = 0; gi < 2; gi++) {
            int g = gp * 2 + gi;
            part[q][g][lane >> 2][2 * (lane & 3)]           = acc[gi][0];
            part[q][g][lane >> 2][2 * (lane & 3) + 1]       = acc[gi][1];
            part[q][g][(lane >> 2) + 8][2 * (lane & 3)]     = acc[gi][2];
            part[q][g][(lane >> 2) + 8][2 * (lane & 3) + 1] = acc[gi][3];
        }
        __syncthreads();

        // cell update (tid < 128)
        float yreg = 0.f;
        if (tid < 128) {
            float v[4];
            #pragma unroll
            for (int g = 0; g < 4; g++)
                v[g] = part[0][g][ub][uj] + part[1][g][ub][uj]
                     + part[2][g][ub][uj] + part[3][g][ub][uj] + xgv[g];
            float gi = sigm(v[0]);
            float gf = sigm(v[1]);
            float gg = tanhf(v[2]);
            float go = sigm(v[3]);
            float cn = gf * creg + gi * gg;
            float hn = go * tanhf(cn);
            bool active = s < len;
            yreg = active ? hn : 0.f;
            if (active) { creg = cn; hreg = hn; }

            unsigned short hb = __half_as_ushort(__float2half_rn(hreg));
            asm volatile("st.global.cg.u16 [%0], %1;"
                         :: "l"(&g_h16[t & 1][dir][ub][u0 + uj]), "h"(hb));
        }
        __syncthreads();

        // publish h(t): release-store step tag to own slot
        if (tid == 0) {
            asm volatile("st.release.gpu.global.u32 [%0], %1;"
                         :: "l"(myslot), "r"((unsigned)(t + 1)));
        }

        // y publish AFTER the release: off the cross-SM critical chain
        if (tid < 128) {
            g_YT[(size_t)(dir * 512 + u0 + uj) * MTOT + s * 16 + ub] = tfr(yreg);
        }
    }
}

// ---------------- head ----------------
__global__ void k_head(const float* __restrict__ W3, const float* __restrict__ b3,
                       float* __restrict__ out) {
    int gw = (blockIdx.x * blockDim.x + threadIdx.x) >> 5;
    int lane = threadIdx.x & 31;
    if (gw >= MTOT) return;
    const float* a = g_A2 + (size_t)gw * KD;
    float s0 = 0, s1 = 0, s2 = 0, s3 = 0, s4 = 0;
    for (int k = lane; k < KD; k += 32) {
        float v = a[k];
        s0 += v * W3[k];
        s1 += v * W3[1024 + k];
        s2 += v * W3[2048 + k];
        s3 += v * W3[3072 + k];
        s4 += v * W3[4096 + k];
    }
    #pragma unroll
    for (int o = 16; o; o >>= 1) {
        s0 += __shfl_down_sync(0xffffffffu, s0, o);
        s1 += __shfl_down_sync(0xffffffffu, s1, o);
        s2 += __shfl_down_sync(0xffffffffu, s2, o);
        s3 += __shfl_down_sync(0xffffffffu, s3, o);
        s4 += __shfl_down_sync(0xffffffffu, s4, o);
    }
    if (lane == 0) {
        int b = gw & 15, s = gw >> 4;
        float* o = out + ((size_t)b * SEQ + s) * 5;
        o[0] = s0 + b3[0];
        o[1] = s1 + b3[1];
        o[2] = s2 + b3[2];
        o[3] = s3 + b3[3];
        o[4] = s4 + b3[4];
    }
}

// ---------------- launch ----------------
extern "C" void kernel_launch(void* const* d_in, const int* in_sizes, int n_in,
                              void* d_out, int out_size) {
    const int*   x    = (const int*)d_in[0];
    const int*   len  = (const int*)d_in[1];
    const float* lang = (const float*)d_in[2];
    const float* emb  = (const float*)d_in[3];
    const float* W_ih = (const float*)d_in[4];
    const float* W_hh = (const float*)d_in[5];
    const float* b_ih = (const float*)d_in[6];
    const float* b_hh = (const float*)d_in[7];
    const float* W1   = (const float*)d_in[8];
    const float* b1   = (const float*)d_in[9];
    const float* W2   = (const float*)d_in[10];
    const float* b2   = (const float*)d_in[11];
    const float* W3   = (const float*)d_in[12];
    const float* b3   = (const float*)d_in[13];
    float* out = (float*)d_out;

    k_embed<<<SEQ, 256>>>(x, lang, emb);

    for (int l = 0; l < 2; l++) {
        // W_ih[l] fp16 + bias + tag reset
        k_cvtW<<<4113, 256>>>(W_ih + (size_t)l * NXG * KD, NXG * KD / 4,
                              b_ih + (size_t)l * NXG, b_hh + (size_t)l * NXG, 1);
        k_gemm<<<dim3(NXG / 256, MTOT / 128), 256>>>(l == 0 ? 0 : 1, nullptr, NXG, 0, 1);
        k_rec<<<128, 256>>>(W_hh + (size_t)l * 2 * 2048 * 512, len);
        // bridge: g_YT [k][m] float -> g_Yh [m][k] fp16 (feeds next GEMM)
        k_t<<<dim3(16, 128), 256>>>();
    }

    k_cvtW<<<1024, 256>>>(W1, KD * KD / 4, nullptr, nullptr, 0);
    k_gemm<<<dim3(KD / 256, MTOT / 128), 256>>>(1, b1, KD, 1, 3);
    k_cvtW<<<1024, 256>>>(W2, KD * KD / 4, nullptr, nullptr, 0);
    k_gemm<<<dim3(KD / 256, MTOT / 128), 256>>>(2, b2, KD, 1, 0);
    k_head<<<MTOT / 8, 256>>>(W3, b3, out);
}